// round 10
// baseline (speedup 1.0000x reference)
#include <cuda_runtime.h>

#define NN 50000
#define NE 500000
#define HH 128
typedef unsigned long long ull;

// Scratch (device globals — allocation-free rule)
__device__ float g_agg[NN * 512];            // aggregated raw neighbor features
__device__ float g_Wt[4 * HH * HH];          // weights transposed [m][k][o]
                                             // m: 0=W_s_root 1=W_s_rel 2=W_v_root 3=W_v_rel
__device__ int g_is64;                       // edge_index dtype flag
__device__ int g_deg[NN];
__device__ int g_cur[NN];
__device__ int g_off[NN + 1];
__device__ int g_ecol[NE];

__device__ __forceinline__ int clampn(int v) {
    return (v < 0) ? 0 : ((v >= NN) ? NN - 1 : v);
}

// ---------------------------------------------------------------------------
// Merged setup: zero counters, probe dtype, transpose weights.
__global__ void setup_kernel(const int* __restrict__ ei32,
                             const float* __restrict__ Wsroot,
                             const float* __restrict__ Wsrel,
                             const float* __restrict__ Wvroot,
                             const float* __restrict__ Wvrel) {
    int i = blockIdx.x * blockDim.x + threadIdx.x;
    if (i < NN) { g_deg[i] = 0; g_cur[i] = 0; }
    if (i == 0) {
        int all_zero = 1;
        #pragma unroll
        for (int q = 0; q < 32; q++)
            if (ei32[2 * q + 1] != 0) all_zero = 0;
        g_is64 = all_zero;
    }
    if (i < 4 * HH * HH) {
        int m = i >> 14;
        int rest = i & (HH * HH - 1);
        int o = rest >> 7;
        int k = rest & 127;
        const float* src = (m == 0) ? Wsroot : (m == 1) ? Wsrel : (m == 2) ? Wvroot : Wvrel;
        g_Wt[(m << 14) + (k << 7) + o] = src[(o << 7) + k];
    }
}

// ---------------------------------------------------------------------------
// CSR build: histogram -> exclusive scan -> scatter (indices clamped).
__global__ void hist_kernel(const void* __restrict__ ei_raw) {
    int e = blockIdx.x * blockDim.x + threadIdx.x;
    if (e >= NE) return;
    int r = g_is64 ? (int)((const long long*)ei_raw)[e]
                   : ((const int*)ei_raw)[e];
    atomicAdd(&g_deg[clampn(r)], 1);
}

__global__ void scan_kernel() {
    __shared__ int sm[1024];
    int t = threadIdx.x;
    const int CH = (NN + 1023) / 1024;   // 49
    int b = t * CH;
    int e = min(b + CH, NN);
    int s = 0;
    for (int i = b; i < e; i++) s += g_deg[i];
    sm[t] = s;
    __syncthreads();
    for (int o = 1; o < 1024; o <<= 1) {
        int v = (t >= o) ? sm[t - o] : 0;
        __syncthreads();
        sm[t] += v;
        __syncthreads();
    }
    int run = (t == 0) ? 0 : sm[t - 1];
    for (int i = b; i < e; i++) { g_off[i] = run; run += g_deg[i]; }
    if (t == 1023) g_off[NN] = sm[1023];
}

__global__ void scatter_kernel(const void* __restrict__ ei_raw) {
    int e = blockIdx.x * blockDim.x + threadIdx.x;
    if (e >= NE) return;
    int r, c;
    if (g_is64) {
        const long long* ei = (const long long*)ei_raw;
        r = (int)ei[e];
        c = (int)ei[NE + e];
    } else {
        const int* ei = (const int*)ei_raw;
        r = ei[e];
        c = ei[NE + e];
    }
    r = clampn(r);
    c = clampn(c);
    int p = atomicAdd(&g_cur[r], 1);
    int slot = g_off[r] + p;
    if (slot >= NE) slot = NE - 1;
    g_ecol[slot] = c;
}

// ---------------------------------------------------------------------------
// Atomic-free gather aggregation (unchanged — proven; at the L2 LTS cap).
#define GW 8
__global__ void gather_kernel(const float4* __restrict__ x4) {
    int w = threadIdx.x >> 5, lane = threadIdx.x & 31;
    const int ngb = NN / GW;            // 6250
    int bid = blockIdx.x;
    int pass = bid / ngb;
    int n = (bid - pass * ngb) * GW + w;
    int beg = g_off[n], end = g_off[n + 1];
    if (beg < 0) beg = 0;
    if (end > NE) end = NE;
    int jo = (pass << 5) + lane;

    float4 a0 = make_float4(0.f, 0.f, 0.f, 0.f);
    float4 a1 = a0;
    int i = beg;
    for (; i + 2 <= end; i += 2) {
        int c0 = g_ecol[i];
        int c1 = g_ecol[i + 1];
        float4 v0 = x4[(size_t)c0 * 128 + jo];
        float4 v1 = x4[(size_t)c1 * 128 + jo];
        a0.x += v0.x; a0.y += v0.y; a0.z += v0.z; a0.w += v0.w;
        a1.x += v1.x; a1.y += v1.y; a1.z += v1.z; a1.w += v1.w;
    }
    if (i < end) {
        int c0 = g_ecol[i];
        float4 v0 = x4[(size_t)c0 * 128 + jo];
        a0.x += v0.x; a0.y += v0.y; a0.z += v0.z; a0.w += v0.w;
    }
    float4 r = make_float4(a0.x + a1.x, a0.y + a1.y, a0.z + a1.z, a0.w + a1.w);
    ((float4*)g_agg)[(size_t)n * 128 + jo] = r;
}

// ---------------------------------------------------------------------------
// Fused GEMM with double-buffered software pipeline.
// Inner compute is R9's proven form (zero A-pack MOVs). Per chunk:
// cp.async W(i+1), LDG A(i+1) -> compute(i) -> STS A(i+1), wait, ONE bar.
__device__ __forceinline__ int rowbase(int is_s, int r, int mlim) {
    r = (r < mlim) ? r : (mlim - 1);
    if (is_s) return r << 9;
    int n = r / 3;
    int ch = r - n * 3;
    return (n << 9) + ((ch + 1) << 7);
}

#define TM 128
#define KT 32
#define AS_STRIDE (TM + 4)                    // 132 floats = 528 B (16B-multiple)
#define ABUF_FLOATS (KT * AS_STRIDE)          // 4224
#define WBUF_FLOATS (KT * HH)                 // 4096
#define GEMM_SMEM_BYTES ((2 * ABUF_FLOATS + 2 * WBUF_FLOATS) * 4)   // 66560

__device__ __forceinline__ void cp_async16(float* dst_smem, const float* src) {
    unsigned sa = (unsigned)__cvta_generic_to_shared(dst_smem);
    asm volatile("cp.async.ca.shared.global [%0], [%1], 16;" :: "r"(sa), "l"(src) : "memory");
}

__global__ __launch_bounds__(256, 2)
void gemm_kernel(const float* __restrict__ x,
                 const float* __restrict__ b_s,
                 float* __restrict__ out,
                 int nb_s) {
    extern __shared__ __align__(16) float smem[];
    float* Abuf[2] = { smem, smem + ABUF_FLOATS };
    float* Wbuf[2] = { smem + 2 * ABUF_FLOATS, smem + 2 * ABUF_FLOATS + WBUF_FLOATS };

    int t = threadIdx.x;
    int bid = (int)blockIdx.x;
    int is_s = (bid < nb_s) ? 1 : 0;
    int row0 = (is_s ? bid : bid - nb_s) * TM;
    int mlim = is_s ? NN : 3 * NN;
    const float* Wroot = g_Wt + (is_s ? 0 : 2 * HH * HH);
    const float* Wrel  = g_Wt + (is_s ? HH * HH : 3 * HH * HH);

    int ox = t & 31;        // output group: outputs ox*4 .. ox*4+3
    int ry = t >> 5;        // warp id: rows ry*16 .. ry*16+15

    // A loader: thread -> row t>>1, k-half (t&1)*16
    int alr = t >> 1;
    int akh = (t & 1) << 4;
    int ab = rowbase(is_s, row0 + alr, mlim);
    // W loader: thread copies 4 float4 of 32x128 chunk
    int wk = t >> 3;
    int wq = t & 7;

    ull acc[8][4];
    #pragma unroll
    for (int p = 0; p < 8; p++)
        #pragma unroll
        for (int j = 0; j < 4; j++) acc[p][j] = 0ULL;

    // ---- prologue: chunk 0 (x / Wroot, kc=0) ----
    {
        const float* wsrc = Wroot + (size_t)wk * HH;
        #pragma unroll
        for (int s = 0; s < 4; s++)
            cp_async16(&Wbuf[0][wk * HH + (wq + 8 * s) * 4], wsrc + (wq + 8 * s) * 4);
        asm volatile("cp.async.commit_group;" ::: "memory");

        #pragma unroll
        for (int q4 = 0; q4 < 4; q4++) {
            float4 a = *(const float4*)(x + ab + akh + q4 * 4);
            Abuf[0][(akh + q4 * 4 + 0) * AS_STRIDE + alr] = a.x;
            Abuf[0][(akh + q4 * 4 + 1) * AS_STRIDE + alr] = a.y;
            Abuf[0][(akh + q4 * 4 + 2) * AS_STRIDE + alr] = a.z;
            Abuf[0][(akh + q4 * 4 + 3) * AS_STRIDE + alr] = a.w;
        }
        asm volatile("cp.async.wait_group 0;" ::: "memory");
        __syncthreads();
    }

    // ---- 8 chunks: i<4 -> (x, Wroot), i>=4 -> (agg, Wrel) ----
    #pragma unroll 1
    for (int i = 0; i < 8; i++) {
        int cur = i & 1;
        float4 ar[4];
        if (i < 7) {
            int nh = (i + 1) >> 2;
            int nkc = ((i + 1) & 3) * KT;
            const float* Wn = nh ? Wrel : Wroot;
            const float* An = nh ? g_agg : x;
            // W(i+1) via cp.async into the other buffer
            const float* wsrc = Wn + (size_t)(nkc + wk) * HH;
            float* wdst = Wbuf[cur ^ 1] + wk * HH;
            #pragma unroll
            for (int s = 0; s < 4; s++)
                cp_async16(wdst + (wq + 8 * s) * 4, wsrc + (wq + 8 * s) * 4);
            asm volatile("cp.async.commit_group;" ::: "memory");
            // A(i+1) into registers (transposed store after compute)
            #pragma unroll
            for (int q4 = 0; q4 < 4; q4++)
                ar[q4] = *(const float4*)(An + ab + nkc + akh + q4 * 4);
        }

        // compute chunk i from buffers [cur]
        const float* As = Abuf[cur];
        const float* Ws = Wbuf[cur];
        #pragma unroll
        for (int k = 0; k < KT; k++) {
            ulonglong2 av[4];
            #pragma unroll
            for (int q = 0; q < 4; q++)
                av[q] = *(const ulonglong2*)(&As[k * AS_STRIDE + ry * 16 + q * 4]);
            float4 w = *(const float4*)(&Ws[k * HH + ox * 4]);
            #pragma unroll
            for (int j = 0; j < 4; j++) {
                float wj = (j == 0) ? w.x : (j == 1) ? w.y : (j == 2) ? w.z : w.w;
                ull wp;
                asm("mov.b64 %0, {%1, %1};" : "=l"(wp) : "f"(wj));
                #pragma unroll
                for (int q = 0; q < 4; q++) {
                    asm("fma.rn.f32x2 %0, %1, %2, %0;"
                        : "+l"(acc[2 * q][j]) : "l"(av[q].x), "l"(wp));
                    asm("fma.rn.f32x2 %0, %1, %2, %0;"
                        : "+l"(acc[2 * q + 1][j]) : "l"(av[q].y), "l"(wp));
                }
            }
        }

        if (i < 7) {
            float* Ad = Abuf[cur ^ 1];
            #pragma unroll
            for (int q4 = 0; q4 < 4; q4++) {
                Ad[(akh + q4 * 4 + 0) * AS_STRIDE + alr] = ar[q4].x;
                Ad[(akh + q4 * 4 + 1) * AS_STRIDE + alr] = ar[q4].y;
                Ad[(akh + q4 * 4 + 2) * AS_STRIDE + alr] = ar[q4].z;
                Ad[(akh + q4 * 4 + 3) * AS_STRIDE + alr] = ar[q4].w;
            }
            asm volatile("cp.async.wait_group 0;" ::: "memory");
            __syncthreads();
        }
    }

    float4 bv = make_float4(0.f, 0.f, 0.f, 0.f);
    if (is_s) bv = *(const float4*)(b_s + ox * 4);

    #pragma unroll
    for (int p = 0; p < 8; p++) {
        int ra = row0 + ry * 16 + 2 * p;
        int rb = ra + 1;
        float lo[4], hi[4];
        #pragma unroll
        for (int j = 0; j < 4; j++)
            asm("mov.b64 {%0,%1}, %2;" : "=f"(lo[j]), "=f"(hi[j]) : "l"(acc[p][j]));
        if (ra < mlim) {
            float* dst = out + rowbase(is_s, ra, mlim) + ox * 4;
            *(float4*)dst = make_float4(lo[0] + bv.x, lo[1] + bv.y, lo[2] + bv.z, lo[3] + bv.w);
        }
        if (rb < mlim) {
            float* dst = out + rowbase(is_s, rb, mlim) + ox * 4;
            *(float4*)dst = make_float4(hi[0] + bv.x, hi[1] + bv.y, hi[2] + bv.z, hi[3] + bv.w);
        }
    }
}

// ---------------------------------------------------------------------------
extern "C" void kernel_launch(void* const* d_in, const int* in_sizes, int n_in,
                              void* d_out, int out_size) {
    const float* x      = (const float*)d_in[0];
    const void*  ei     = d_in[1];
    const float* Wsrel  = (const float*)d_in[2];
    const float* Wsroot = (const float*)d_in[3];
    const float* bsroot = (const float*)d_in[4];
    const float* Wvrel  = (const float*)d_in[5];
    const float* Wvroot = (const float*)d_in[6];
    float* out = (float*)d_out;

    static int smem_set = 0;
    if (!smem_set) {
        cudaFuncSetAttribute(gemm_kernel, cudaFuncAttributeMaxDynamicSharedMemorySize,
                             GEMM_SMEM_BYTES);
        smem_set = 1;
    }

    setup_kernel<<<(4 * HH * HH + 255) / 256, 256>>>((const int*)ei, Wsroot, Wsrel, Wvroot, Wvrel);

    hist_kernel<<<(NE + 255) / 256, 256>>>(ei);
    scan_kernel<<<1, 1024>>>();
    scatter_kernel<<<(NE + 255) / 256, 256>>>(ei);

    gather_kernel<<<4 * (NN / GW), 256>>>((const float4*)x);

    int nb_s = (NN + TM - 1) / TM;            // 391
    int nb_v = (3 * NN + TM - 1) / TM;        // 1172
    gemm_kernel<<<nb_s + nb_v, 256, GEMM_SMEM_BYTES>>>(x, bsroot, out, nb_s);
}